// round 1
// baseline (speedup 1.0000x reference)
#include <cuda_runtime.h>
#include <math.h>

// ---------------- problem constants ----------------
#define Bb   4
#define Tt   8000
#define DIMN 512
#define Hh   8
#define DHd  64
#define Cc   200
#define NBb  40
#define Mm   (Bb*Tt)        // 32000
#define NJ   (Bb*NBb*Hh)    // 1280
#define RPAD 256
#define SCALE 0.125f

// ---------------- scratch (device globals; no allocation allowed) ----------------
__device__ float g_xn [Mm*DIMN];
__device__ float g_q  [Mm*DIMN];
__device__ float g_kv [Mm*2*DIMN];
__device__ float g_rel[Cc*Cc*DHd];
__device__ float g_pos[(size_t)NJ*Cc*RPAD];   // [j][c][r padded to 256], scaled
__device__ float g_att[Mm*DIMN];

// ---------------- LayerNorm: one block per row ----------------
__global__ void ln_kernel(const float* __restrict__ x,
                          const float* __restrict__ g,
                          const float* __restrict__ bta) {
    int row = blockIdx.x;
    int t = threadIdx.x;                       // 128 threads, 1 float4 each
    float4 v = ((const float4*)(x + (size_t)row*DIMN))[t];
    float s  = v.x + v.y + v.z + v.w;
    float ss = v.x*v.x + v.y*v.y + v.z*v.z + v.w*v.w;
    #pragma unroll
    for (int o = 16; o; o >>= 1) {
        s  += __shfl_xor_sync(~0u, s,  o);
        ss += __shfl_xor_sync(~0u, ss, o);
    }
    __shared__ float rs[4], rss[4];
    int w = t >> 5;
    if ((t & 31) == 0) { rs[w] = s; rss[w] = ss; }
    __syncthreads();
    s  = rs[0]  + rs[1]  + rs[2]  + rs[3];
    ss = rss[0] + rss[1] + rss[2] + rss[3];
    float mu  = s  * (1.0f/DIMN);
    float var = ss * (1.0f/DIMN) - mu*mu;
    float inv = rsqrtf(var + 1e-5f);
    float4 gg = ((const float4*)g)[t];
    float4 bb = ((const float4*)bta)[t];
    float4 o;
    o.x = (v.x-mu)*inv*gg.x + bb.x;
    o.y = (v.y-mu)*inv*gg.y + bb.y;
    o.z = (v.z-mu)*inv*gg.z + bb.z;
    o.w = (v.w-mu)*inv*gg.w + bb.w;
    ((float4*)(g_xn + (size_t)row*DIMN))[t] = o;
}

// ---------------- rel gather: rel[c][r][d] = pos_emb[dists[c][r]][d] ----------------
__global__ void gather_kernel(const int* __restrict__ dists,
                              const float* __restrict__ pe) {
    int idx = blockIdx.x*256 + threadIdx.x;
    if (idx < Cc*Cc*DHd) {
        int cr = idx >> 6, d = idx & 63;
        g_rel[idx] = pe[dists[cr]*DHd + d];
    }
}

// ---------------- generic fp32 GEMM: out(M x N) = A(M x 512) @ W(512 x N) [+ bias] ----------------
__global__ __launch_bounds__(256)
void gemm_kernel(const float* __restrict__ A, const float* __restrict__ W,
                 const float* __restrict__ bias, float* __restrict__ out, int N) {
    __shared__ float As[16][64];     // [k][m]
    __shared__ float Bsm[16][68];    // [k][n], padded
    int tid = threadIdx.x;
    int m0 = blockIdx.y*64, n0 = blockIdx.x*64;
    int ty = tid >> 4, tx = tid & 15;        // 16x16, 4x4 micro-tile
    int ar = tid >> 2, ak = (tid & 3) * 4;   // A tile load
    int bk = tid >> 4, bc = (tid & 15) * 4;  // W tile load
    float acc[4][4] = {};
    for (int k0 = 0; k0 < DIMN; k0 += 16) {
        float4 av = *(const float4*)(A + (size_t)(m0+ar)*DIMN + k0 + ak);
        As[ak+0][ar] = av.x; As[ak+1][ar] = av.y;
        As[ak+2][ar] = av.z; As[ak+3][ar] = av.w;
        *(float4*)&Bsm[bk][bc] = *(const float4*)(W + (size_t)(k0+bk)*N + n0 + bc);
        __syncthreads();
        #pragma unroll
        for (int k = 0; k < 16; k++) {
            float4 a = *(const float4*)&As[k][ty*4];
            float4 b = *(const float4*)&Bsm[k][tx*4];
            float ai[4] = {a.x, a.y, a.z, a.w};
            float bj[4] = {b.x, b.y, b.z, b.w};
            #pragma unroll
            for (int i = 0; i < 4; i++)
                #pragma unroll
                for (int j = 0; j < 4; j++)
                    acc[i][j] += ai[i]*bj[j];
        }
        __syncthreads();
    }
    float bv[4] = {0.f, 0.f, 0.f, 0.f};
    if (bias) {
        bv[0] = bias[n0+tx*4+0]; bv[1] = bias[n0+tx*4+1];
        bv[2] = bias[n0+tx*4+2]; bv[3] = bias[n0+tx*4+3];
    }
    #pragma unroll
    for (int i = 0; i < 4; i++) {
        float4 o = make_float4(acc[i][0]+bv[0], acc[i][1]+bv[1],
                               acc[i][2]+bv[2], acc[i][3]+bv[3]);
        *(float4*)(out + (size_t)(m0+ty*4+i)*N + n0 + tx*4) = o;
    }
}

// ---------------- pos bias: per (c, j-tile) block, P[j][c][r] = SCALE * rel[c] @ q_c ----------------
// smem: rel_s [64 k][204 r-pad], qt [64 k][65 j-pad]  (68,864 B dynamic)
__global__ __launch_bounds__(256)
void pos_kernel() {
    extern __shared__ float sm[];
    float* rel_s = sm;                // 64*204
    float* qt    = sm + 64*204;       // 64*65
    int tid = threadIdx.x;
    int c  = blockIdx.y;
    int j0 = blockIdx.x * 64;
    for (int idx = tid; idx < Cc*DHd; idx += 256) {
        int r = idx >> 6, d = idx & 63;
        rel_s[d*204 + r] = g_rel[((size_t)c*Cc + r)*DHd + d];
    }
    for (int idx = tid; idx < 64*64; idx += 256) {
        int jj = idx >> 6, d = idx & 63;
        int j = j0 + jj;
        int b = j / (NBb*Hh), m = (j / Hh) % NBb, h = j & 7;
        qt[d*65 + jj] = g_q[(size_t)(b*Tt + m*Cc + c)*DIMN + h*DHd + d];
    }
    __syncthreads();
    int rt = tid & 31, ty = tid >> 5;      // lane -> 4 consecutive r; warp -> 8 j
    #pragma unroll
    for (int pass = 0; pass < 2; pass++) {
        int rb = pass * 128;
        float acc[4][8];
        #pragma unroll
        for (int i = 0; i < 4; i++)
            #pragma unroll
            for (int jj = 0; jj < 8; jj++) acc[i][jj] = 0.f;
        #pragma unroll 4
        for (int k = 0; k < 64; k++) {
            float4 rv = *(const float4*)&rel_s[k*204 + rb + rt*4];
            #pragma unroll
            for (int jj = 0; jj < 8; jj++) {
                float qv = qt[k*65 + ty*8 + jj];
                acc[0][jj] += rv.x*qv; acc[1][jj] += rv.y*qv;
                acc[2][jj] += rv.z*qv; acc[3][jj] += rv.w*qv;
            }
        }
        #pragma unroll
        for (int jj = 0; jj < 8; jj++) {
            int j = j0 + ty*8 + jj;
            float4 o = make_float4(acc[0][jj]*SCALE, acc[1][jj]*SCALE,
                                   acc[2][jj]*SCALE, acc[3][jj]*SCALE);
            *(float4*)&g_pos[((size_t)j*Cc + c)*RPAD + rb + rt*4] = o;
        }
    }
}

// ---------------- fused attention: one block per (b, m, h); 4 queries per warp ----------------
// smem: Ks[64][201] + Vs[200][64] + Qs[32][64] + Ps[32][200] = 136,448 B dynamic
__global__ __launch_bounds__(256)
void attn_kernel() {
    extern __shared__ float sm[];
    float* Ks = sm;                    // 64*201 (K transposed, padded)
    float* Vs = Ks + 64*201;           // 200*64
    float* Qs = Vs + Cc*DHd;           // 32*64
    float* Ps = Qs + 32*64;            // 32*200
    int tid = threadIdx.x;
    int j = blockIdx.x;
    int b = j / (NBb*Hh), m = (j / Hh) % NBb, h = j & 7;
    int t0 = b*Tt + m*Cc;
    const float* kvb = g_kv + (size_t)t0*(2*DIMN) + h*DHd;
    for (int idx = tid; idx < Cc*DHd; idx += 256) {
        int r = idx >> 6, d = idx & 63;
        Ks[d*201 + r] = kvb[(size_t)r*(2*DIMN) + d];
        Vs[idx]       = kvb[(size_t)r*(2*DIMN) + DIMN + d];
    }
    __syncthreads();
    int w = tid >> 5, l = tid & 31;
    const float* qb   = g_q   + (size_t)t0*DIMN + h*DHd;
    float*       ob   = g_att + (size_t)t0*DIMN + h*DHd;
    const float* posb = g_pos + (size_t)j*Cc*RPAD;

    for (int qbase = 0; qbase < Cc; qbase += 32) {
        int cw = qbase + w*4;
        #pragma unroll
        for (int qq = 0; qq < 4; qq++) {
            int c = cw + qq;
            if (c < Cc) {
                Qs[(w*4+qq)*64 + l]      = qb[(size_t)c*DIMN + l];
                Qs[(w*4+qq)*64 + l + 32] = qb[(size_t)c*DIMN + l + 32];
            }
        }
        __syncwarp();
        float s[4][7];
        #pragma unroll
        for (int qq = 0; qq < 4; qq++)
            #pragma unroll
            for (int i = 0; i < 7; i++) s[qq][i] = 0.f;
        #pragma unroll 2
        for (int d = 0; d < 64; d++) {
            float kc[7];
            #pragma unroll
            for (int i = 0; i < 7; i++) kc[i] = Ks[d*201 + l + 32*i];
            #pragma unroll
            for (int qq = 0; qq < 4; qq++) {
                float qv = Qs[(w*4+qq)*64 + d];
                #pragma unroll
                for (int i = 0; i < 7; i++) s[qq][i] += qv*kc[i];
            }
        }
        #pragma unroll
        for (int qq = 0; qq < 4; qq++) {
            int c = cw + qq;
            if (c >= Cc) continue;                 // warp-uniform
            const float* pp = posb + (size_t)c*RPAD;
            float mx = -1e30f;
            #pragma unroll
            for (int i = 0; i < 7; i++) {
                int r = l + 32*i;
                float v = (r < Cc) ? (s[qq][i]*SCALE + pp[r]) : -1e30f;
                s[qq][i] = v;
                mx = fmaxf(mx, v);
            }
            #pragma unroll
            for (int o = 16; o; o >>= 1) mx = fmaxf(mx, __shfl_xor_sync(~0u, mx, o));
            float sum = 0.f;
            #pragma unroll
            for (int i = 0; i < 7; i++) {
                float e = (l + 32*i < Cc) ? __expf(s[qq][i] - mx) : 0.f;
                s[qq][i] = e; sum += e;
            }
            #pragma unroll
            for (int o = 16; o; o >>= 1) sum += __shfl_xor_sync(~0u, sum, o);
            float inv = 1.f / sum;
            #pragma unroll
            for (int i = 0; i < 7; i++) {
                int r = l + 32*i;
                if (r < Cc) Ps[(w*4+qq)*Cc + r] = s[qq][i]*inv;
            }
        }
        __syncwarp();
        float a0[4] = {0,0,0,0}, a1[4] = {0,0,0,0};
        #pragma unroll 4
        for (int r = 0; r < Cc; r++) {
            float v0 = Vs[r*64 + l], v1 = Vs[r*64 + l + 32];
            #pragma unroll
            for (int qq = 0; qq < 4; qq++) {
                float p = Ps[(w*4+qq)*Cc + r];
                a0[qq] += p*v0; a1[qq] += p*v1;
            }
        }
        #pragma unroll
        for (int qq = 0; qq < 4; qq++) {
            int c = cw + qq;
            if (c < Cc) {
                ob[(size_t)c*DIMN + l]      = a0[qq];
                ob[(size_t)c*DIMN + l + 32] = a1[qq];
            }
        }
        __syncwarp();
    }
}

// ---------------- launch ----------------
extern "C" void kernel_launch(void* const* d_in, const int* in_sizes, int n_in,
                              void* d_out, int out_size) {
    const float* x    = (const float*)d_in[0];
    const int*   dst  = (const int*)  d_in[1];
    const float* lng  = (const float*)d_in[2];
    const float* lnb  = (const float*)d_in[3];
    const float* Wq   = (const float*)d_in[4];
    const float* Wkv  = (const float*)d_in[5];
    const float* pe   = (const float*)d_in[6];
    const float* Wo   = (const float*)d_in[7];
    const float* bo   = (const float*)d_in[8];
    float* out = (float*)d_out;

    void* tmp;
    cudaGetSymbolAddress(&tmp, g_xn);  float* xn  = (float*)tmp;
    cudaGetSymbolAddress(&tmp, g_q);   float* q   = (float*)tmp;
    cudaGetSymbolAddress(&tmp, g_kv);  float* kv  = (float*)tmp;
    cudaGetSymbolAddress(&tmp, g_att); float* att = (float*)tmp;

    cudaFuncSetAttribute(pos_kernel,  cudaFuncAttributeMaxDynamicSharedMemorySize, 68864);
    cudaFuncSetAttribute(attn_kernel, cudaFuncAttributeMaxDynamicSharedMemorySize, 136448);

    ln_kernel<<<Mm, 128>>>(x, lng, lnb);
    gather_kernel<<<(Cc*Cc*DHd + 255)/256, 256>>>(dst, pe);
    gemm_kernel<<<dim3(DIMN/64,   Mm/64), 256>>>(xn, Wq,  nullptr, q,  DIMN);
    gemm_kernel<<<dim3(2*DIMN/64, Mm/64), 256>>>(xn, Wkv, nullptr, kv, 2*DIMN);
    pos_kernel<<<dim3(NJ/64, Cc), 256, 68864>>>();
    attn_kernel<<<NJ, 256, 136448>>>();
    gemm_kernel<<<dim3(DIMN/64, Mm/64), 256>>>(att, Wo, bo, out, DIMN);
}

// round 2
// speedup vs baseline: 1.8627x; 1.8627x over previous
#include <cuda_runtime.h>
#include <math.h>

// ---------------- problem constants ----------------
#define Bb   4
#define Tt   8000
#define DIMN 512
#define Hh   8
#define DHd  64
#define Cc   200
#define NBb  40
#define Mm   (Bb*Tt)        // 32000
#define NJ   (Bb*NBb*Hh)    // 1280
#define RPAD 256
#define SCALE 0.125f

// ---------------- scratch (device globals; no allocation allowed) ----------------
__device__ float g_xn [Mm*DIMN];
__device__ float g_q  [Mm*DIMN];
__device__ float g_kv [Mm*2*DIMN];
__device__ float g_rel[Cc*Cc*DHd];
__device__ float g_pos[(size_t)NJ*Cc*RPAD];   // [j][c][r padded to 256], scaled
__device__ float g_att[Mm*DIMN];
__device__ float g_wq [DIMN*DIMN];
__device__ float g_wkv[DIMN*2*DIMN];
__device__ float g_wo [DIMN*DIMN];

__device__ __forceinline__ unsigned f2tf32(float f) {
    unsigned u; asm("cvt.rna.tf32.f32 %0, %1;" : "=r"(u) : "f"(f)); return u;
}

// ---------------- pre-round weights to tf32 bit-pattern ----------------
__global__ void round_kernel(const float* __restrict__ src, float* __restrict__ dst, int n4) {
    int i = blockIdx.x*256 + threadIdx.x;
    if (i < n4) {
        float4 v = ((const float4*)src)[i];
        uint4 o = make_uint4(f2tf32(v.x), f2tf32(v.y), f2tf32(v.z), f2tf32(v.w));
        ((uint4*)dst)[i] = o;
    }
}

// ---------------- LayerNorm: one block per row (stores tf32-rounded) ----------------
__global__ void ln_kernel(const float* __restrict__ x,
                          const float* __restrict__ g,
                          const float* __restrict__ bta) {
    int row = blockIdx.x;
    int t = threadIdx.x;                       // 128 threads, 1 float4 each
    float4 v = ((const float4*)(x + (size_t)row*DIMN))[t];
    float s  = v.x + v.y + v.z + v.w;
    float ss = v.x*v.x + v.y*v.y + v.z*v.z + v.w*v.w;
    #pragma unroll
    for (int o = 16; o; o >>= 1) {
        s  += __shfl_xor_sync(~0u, s,  o);
        ss += __shfl_xor_sync(~0u, ss, o);
    }
    __shared__ float rs[4], rss[4];
    int w = t >> 5;
    if ((t & 31) == 0) { rs[w] = s; rss[w] = ss; }
    __syncthreads();
    s  = rs[0]  + rs[1]  + rs[2]  + rs[3];
    ss = rss[0] + rss[1] + rss[2] + rss[3];
    float mu  = s  * (1.0f/DIMN);
    float var = ss * (1.0f/DIMN) - mu*mu;
    float inv = rsqrtf(var + 1e-5f);
    float4 gg = ((const float4*)g)[t];
    float4 bb = ((const float4*)bta)[t];
    uint4 o;
    o.x = f2tf32((v.x-mu)*inv*gg.x + bb.x);
    o.y = f2tf32((v.y-mu)*inv*gg.y + bb.y);
    o.z = f2tf32((v.z-mu)*inv*gg.z + bb.z);
    o.w = f2tf32((v.w-mu)*inv*gg.w + bb.w);
    ((uint4*)(g_xn + (size_t)row*DIMN))[t] = o;
}

// ---------------- rel gather: rel[c][r][d] = pos_emb[dists[c][r]][d] ----------------
__global__ void gather_kernel(const int* __restrict__ dists,
                              const float* __restrict__ pe) {
    int idx = blockIdx.x*256 + threadIdx.x;
    if (idx < Cc*Cc*DHd) {
        int cr = idx >> 6, d = idx & 63;
        g_rel[idx] = pe[dists[cr]*DHd + d];
    }
}

// ---------------- tf32 tensor-core GEMM: out(M x N) = A(M x 512) @ W(512 x N) [+bias] ----
// BM=128 BN=128 BK=16, 256 threads (8 warps 2x4), warp tile 64x32, mma m16n8k8.
// Operands must already be tf32-rounded floats.
#define BM 128
#define BN 128
#define BK 16
#define AST 136

__device__ __forceinline__ void mma8(float* c, const unsigned* a, const unsigned* b) {
    asm volatile("mma.sync.aligned.m16n8k8.row.col.f32.tf32.tf32.f32 "
        "{%0,%1,%2,%3}, {%4,%5,%6,%7}, {%8,%9}, {%0,%1,%2,%3};"
        : "+f"(c[0]), "+f"(c[1]), "+f"(c[2]), "+f"(c[3])
        : "r"(a[0]), "r"(a[1]), "r"(a[2]), "r"(a[3]), "r"(b[0]), "r"(b[1]));
}

__global__ __launch_bounds__(256)
void gemm_tf32(const float* __restrict__ A, const float* __restrict__ W,
               const float* __restrict__ bias, float* __restrict__ out, int N) {
    __shared__ unsigned As[2][BK][AST];
    __shared__ unsigned Bs[2][BK][AST];
    int tid  = threadIdx.x;
    int lane = tid & 31, warp = tid >> 5;
    int wm = warp >> 2, wn = warp & 3;        // 2 x 4 warp grid
    int m0 = blockIdx.y*BM, n0 = blockIdx.x*BN;

    int ar = tid >> 2;                         // A row 0..63 (and +64)
    int ak = (tid & 3) * 4;                    // A k offset
    int ag = tid & 3;                          // swizzle group = (k>>2)&3
    int bk = tid >> 4;                         // B k row 0..15
    int bn = (tid & 15) * 4;                   // B n offset (and +64)

    const float* Aptr = A + (size_t)(m0 + ar)*DIMN + ak;
    const float* Wptr = W + (size_t)bk*N + n0 + bn;

    float acc[4][4][4];
    #pragma unroll
    for (int i=0;i<4;i++)
        #pragma unroll
        for (int j=0;j<4;j++)
            #pragma unroll
            for (int r=0;r<4;r++) acc[i][j][r]=0.f;

    // prologue: stage 0
    {
        float4 a0v = *(const float4*)(Aptr);
        float4 a1v = *(const float4*)(Aptr + (size_t)64*DIMN);
        unsigned d0 = (unsigned)__cvta_generic_to_shared(&Bs[0][bk][bn]);
        unsigned d1 = (unsigned)__cvta_generic_to_shared(&Bs[0][bk][bn+64]);
        asm volatile("cp.async.cg.shared.global [%0], [%1], 16;" :: "r"(d0), "l"(Wptr));
        asm volatile("cp.async.cg.shared.global [%0], [%1], 16;" :: "r"(d1), "l"(Wptr+64));
        asm volatile("cp.async.commit_group;");
        int c0 = ar ^ (ag<<3), c1 = (ar+64) ^ (ag<<3);
        As[0][ak+0][c0]=__float_as_uint(a0v.x); As[0][ak+1][c0]=__float_as_uint(a0v.y);
        As[0][ak+2][c0]=__float_as_uint(a0v.z); As[0][ak+3][c0]=__float_as_uint(a0v.w);
        As[0][ak+0][c1]=__float_as_uint(a1v.x); As[0][ak+1][c1]=__float_as_uint(a1v.y);
        As[0][ak+2][c1]=__float_as_uint(a1v.z); As[0][ak+3][c1]=__float_as_uint(a1v.w);
        asm volatile("cp.async.wait_group 0;");
        __syncthreads();
    }

    int buf = 0;
    for (int k0 = BK; k0 <= DIMN; k0 += BK) {
        float4 a0v, a1v;
        if (k0 < DIMN) {
            a0v = *(const float4*)(Aptr + k0);
            a1v = *(const float4*)(Aptr + (size_t)64*DIMN + k0);
            unsigned d0 = (unsigned)__cvta_generic_to_shared(&Bs[buf^1][bk][bn]);
            unsigned d1 = (unsigned)__cvta_generic_to_shared(&Bs[buf^1][bk][bn+64]);
            const float* wp = Wptr + (size_t)k0*N;
            asm volatile("cp.async.cg.shared.global [%0], [%1], 16;" :: "r"(d0), "l"(wp));
            asm volatile("cp.async.cg.shared.global [%0], [%1], 16;" :: "r"(d1), "l"(wp+64));
            asm volatile("cp.async.commit_group;");
        }
        #pragma unroll
        for (int ks = 0; ks < 2; ks++) {
            unsigned af[4][4], bf[4][2];
            int kr = ks*8 + (lane & 3);
            int g0 = (2*ks) << 3, g1 = (2*ks+1) << 3;
            #pragma unroll
            for (int mt = 0; mt < 4; mt++) {
                int mb = wm*64 + mt*16 + (lane>>2);
                af[mt][0] = As[buf][kr  ][ mb    ^ g0];
                af[mt][1] = As[buf][kr  ][(mb+8) ^ g0];
                af[mt][2] = As[buf][kr+4][ mb    ^ g1];
                af[mt][3] = As[buf][kr+4][(mb+8) ^ g1];
            }
            #pragma unroll
            for (int nt = 0; nt < 4; nt++) {
                int nb = wn*32 + nt*8 + (lane>>2);
                bf[nt][0] = Bs[buf][kr  ][nb];
                bf[nt][1] = Bs[buf][kr+4][nb];
            }
            #pragma unroll
            for (int mt = 0; mt < 4; mt++)
                #pragma unroll
                for (int nt = 0; nt < 4; nt++)
                    mma8(acc[mt][nt], af[mt], bf[nt]);
        }
        if (k0 < DIMN) {
            int c0 = ar ^ (ag<<3), c1 = (ar+64) ^ (ag<<3);
            As[buf^1][ak+0][c0]=__float_as_uint(a0v.x); As[buf^1][ak+1][c0]=__float_as_uint(a0v.y);
            As[buf^1][ak+2][c0]=__float_as_uint(a0v.z); As[buf^1][ak+3][c0]=__float_as_uint(a0v.w);
            As[buf^1][ak+0][c1]=__float_as_uint(a1v.x); As[buf^1][ak+1][c1]=__float_as_uint(a1v.y);
            As[buf^1][ak+2][c1]=__float_as_uint(a1v.z); As[buf^1][ak+3][c1]=__float_as_uint(a1v.w);
            asm volatile("cp.async.wait_group 0;");
            __syncthreads();
            buf ^= 1;
        }
    }

    // epilogue
    #pragma unroll
    for (int mt = 0; mt < 4; mt++) {
        int row = m0 + wm*64 + mt*16 + (lane>>2);
        #pragma unroll
        for (int nt = 0; nt < 4; nt++) {
            int col = n0 + wn*32 + nt*8 + (lane&3)*2;
            float bv0 = 0.f, bv1 = 0.f;
            if (bias) { bv0 = bias[col]; bv1 = bias[col+1]; }
            *(float2*)(out + (size_t)row*N + col) =
                make_float2(acc[mt][nt][0]+bv0, acc[mt][nt][1]+bv1);
            *(float2*)(out + (size_t)(row+8)*N + col) =
                make_float2(acc[mt][nt][2]+bv0, acc[mt][nt][3]+bv1);
        }
    }
}

// ---------------- pos bias: per (c, j-tile) block, P[j][c][r] = SCALE * rel[c] @ q_c ----------------
// smem: rel_s [64 k][204 r-pad], qt [64 k][65 j-pad]  (68,864 B dynamic)
__global__ __launch_bounds__(256)
void pos_kernel() {
    extern __shared__ float sm[];
    float* rel_s = sm;                // 64*204
    float* qt    = sm + 64*204;       // 64*65
    int tid = threadIdx.x;
    int c  = blockIdx.y;
    int j0 = blockIdx.x * 64;
    for (int idx = tid; idx < Cc*DHd; idx += 256) {
        int r = idx >> 6, d = idx & 63;
        rel_s[d*204 + r] = g_rel[((size_t)c*Cc + r)*DHd + d];
    }
    for (int idx = tid; idx < 64*64; idx += 256) {
        int jj = idx >> 6, d = idx & 63;
        int j = j0 + jj;
        int b = j / (NBb*Hh), m = (j / Hh) % NBb, h = j & 7;
        qt[d*65 + jj] = g_q[(size_t)(b*Tt + m*Cc + c)*DIMN + h*DHd + d];
    }
    __syncthreads();
    int rt = tid & 31, ty = tid >> 5;      // lane -> 4 consecutive r; warp -> 8 j
    #pragma unroll
    for (int pass = 0; pass < 2; pass++) {
        int rb = pass * 128;
        float acc[4][8];
        #pragma unroll
        for (int i = 0; i < 4; i++)
            #pragma unroll
            for (int jj = 0; jj < 8; jj++) acc[i][jj] = 0.f;
        #pragma unroll 4
        for (int k = 0; k < 64; k++) {
            float4 rv = *(const float4*)&rel_s[k*204 + rb + rt*4];
            #pragma unroll
            for (int jj = 0; jj < 8; jj++) {
                float qv = qt[k*65 + ty*8 + jj];
                acc[0][jj] += rv.x*qv; acc[1][jj] += rv.y*qv;
                acc[2][jj] += rv.z*qv; acc[3][jj] += rv.w*qv;
            }
        }
        #pragma unroll
        for (int jj = 0; jj < 8; jj++) {
            int j = j0 + ty*8 + jj;
            float4 o = make_float4(acc[0][jj]*SCALE, acc[1][jj]*SCALE,
                                   acc[2][jj]*SCALE, acc[3][jj]*SCALE);
            *(float4*)&g_pos[((size_t)j*Cc + c)*RPAD + rb + rt*4] = o;
        }
    }
}

// ---------------- fused attention: one block per (b, m, h); 4 queries per warp ----------------
// smem: Ks[64][201] + Vs[200][64] + Qs[32][64] + Ps[32][200] = 136,448 B dynamic
__global__ __launch_bounds__(256)
void attn_kernel() {
    extern __shared__ float sm[];
    float* Ks = sm;                    // 64*201 (K transposed, padded)
    float* Vs = Ks + 64*201;           // 200*64
    float* Qs = Vs + Cc*DHd;           // 32*64
    float* Ps = Qs + 32*64;            // 32*200
    int tid = threadIdx.x;
    int j = blockIdx.x;
    int b = j / (NBb*Hh), m = (j / Hh) % NBb, h = j & 7;
    int t0 = b*Tt + m*Cc;
    const float* kvb = g_kv + (size_t)t0*(2*DIMN) + h*DHd;
    for (int idx = tid; idx < Cc*DHd; idx += 256) {
        int r = idx >> 6, d = idx & 63;
        Ks[d*201 + r] = kvb[(size_t)r*(2*DIMN) + d];
        Vs[idx]       = kvb[(size_t)r*(2*DIMN) + DIMN + d];
    }
    __syncthreads();
    int w = tid >> 5, l = tid & 31;
    const float* qb   = g_q   + (size_t)t0*DIMN + h*DHd;
    float*       ob   = g_att + (size_t)t0*DIMN + h*DHd;
    const float* posb = g_pos + (size_t)j*Cc*RPAD;

    for (int qbase = 0; qbase < Cc; qbase += 32) {
        int cw = qbase + w*4;
        #pragma unroll
        for (int qq = 0; qq < 4; qq++) {
            int c = cw + qq;
            if (c < Cc) {
                Qs[(w*4+qq)*64 + l]      = qb[(size_t)c*DIMN + l];
                Qs[(w*4+qq)*64 + l + 32] = qb[(size_t)c*DIMN + l + 32];
            }
        }
        __syncwarp();
        float s[4][7];
        #pragma unroll
        for (int qq = 0; qq < 4; qq++)
            #pragma unroll
            for (int i = 0; i < 7; i++) s[qq][i] = 0.f;
        #pragma unroll 2
        for (int d = 0; d < 64; d++) {
            float kc[7];
            #pragma unroll
            for (int i = 0; i < 7; i++) kc[i] = Ks[d*201 + l + 32*i];
            #pragma unroll
            for (int qq = 0; qq < 4; qq++) {
                float qv = Qs[(w*4+qq)*64 + d];
                #pragma unroll
                for (int i = 0; i < 7; i++) s[qq][i] += qv*kc[i];
            }
        }
        #pragma unroll
        for (int qq = 0; qq < 4; qq++) {
            int c = cw + qq;
            if (c >= Cc) continue;                 // warp-uniform
            const float* pp = posb + (size_t)c*RPAD;
            float mx = -1e30f;
            #pragma unroll
            for (int i = 0; i < 7; i++) {
                int r = l + 32*i;
                float v = (r < Cc) ? (s[qq][i]*SCALE + pp[r]) : -1e30f;
                s[qq][i] = v;
                mx = fmaxf(mx, v);
            }
            #pragma unroll
            for (int o = 16; o; o >>= 1) mx = fmaxf(mx, __shfl_xor_sync(~0u, mx, o));
            float sum = 0.f;
            #pragma unroll
            for (int i = 0; i < 7; i++) {
                float e = (l + 32*i < Cc) ? __expf(s[qq][i] - mx) : 0.f;
                s[qq][i] = e; sum += e;
            }
            #pragma unroll
            for (int o = 16; o; o >>= 1) sum += __shfl_xor_sync(~0u, sum, o);
            float inv = 1.f / sum;
            #pragma unroll
            for (int i = 0; i < 7; i++) {
                int r = l + 32*i;
                if (r < Cc) Ps[(w*4+qq)*Cc + r] = s[qq][i]*inv;
            }
        }
        __syncwarp();
        float a0[4] = {0,0,0,0}, a1[4] = {0,0,0,0};
        #pragma unroll 4
        for (int r = 0; r < Cc; r++) {
            float v0 = Vs[r*64 + l], v1 = Vs[r*64 + l + 32];
            #pragma unroll
            for (int qq = 0; qq < 4; qq++) {
                float p = Ps[(w*4+qq)*Cc + r];
                a0[qq] += p*v0; a1[qq] += p*v1;
            }
        }
        #pragma unroll
        for (int qq = 0; qq < 4; qq++) {
            int c = cw + qq;
            if (c < Cc) {
                ob[(size_t)c*DIMN + l]      = __uint_as_float(f2tf32(a0[qq]));
                ob[(size_t)c*DIMN + l + 32] = __uint_as_float(f2tf32(a1[qq]));
            }
        }
        __syncwarp();
    }
}

// ---------------- launch ----------------
extern "C" void kernel_launch(void* const* d_in, const int* in_sizes, int n_in,
                              void* d_out, int out_size) {
    const float* x    = (const float*)d_in[0];
    const int*   dst  = (const int*)  d_in[1];
    const float* lng  = (const float*)d_in[2];
    const float* lnb  = (const float*)d_in[3];
    const float* Wq   = (const float*)d_in[4];
    const float* Wkv  = (const float*)d_in[5];
    const float* pe   = (const float*)d_in[6];
    const float* Wo   = (const float*)d_in[7];
    const float* bo   = (const float*)d_in[8];
    float* out = (float*)d_out;

    void* tmp;
    cudaGetSymbolAddress(&tmp, g_xn);  float* xn  = (float*)tmp;
    cudaGetSymbolAddress(&tmp, g_q);   float* q   = (float*)tmp;
    cudaGetSymbolAddress(&tmp, g_kv);  float* kv  = (float*)tmp;
    cudaGetSymbolAddress(&tmp, g_att); float* att = (float*)tmp;
    cudaGetSymbolAddress(&tmp, g_wq);  float* wq  = (float*)tmp;
    cudaGetSymbolAddress(&tmp, g_wkv); float* wkv = (float*)tmp;
    cudaGetSymbolAddress(&tmp, g_wo);  float* wo  = (float*)tmp;

    cudaFuncSetAttribute(pos_kernel,  cudaFuncAttributeMaxDynamicSharedMemorySize, 68864);
    cudaFuncSetAttribute(attn_kernel, cudaFuncAttributeMaxDynamicSharedMemorySize, 136448);

    round_kernel<<<(DIMN*DIMN/4 + 255)/256, 256>>>(Wq,  wq,  DIMN*DIMN/4);
    round_kernel<<<(DIMN*2*DIMN/4 + 255)/256, 256>>>(Wkv, wkv, DIMN*2*DIMN/4);
    round_kernel<<<(DIMN*DIMN/4 + 255)/256, 256>>>(Wo,  wo,  DIMN*DIMN/4);

    ln_kernel<<<Mm, 128>>>(x, lng, lnb);
    gather_kernel<<<(Cc*Cc*DHd + 255)/256, 256>>>(dst, pe);
    gemm_tf32<<<dim3(DIMN/BN,   Mm/BM), 256>>>(xn, wq,  nullptr, q,  DIMN);
    gemm_tf32<<<dim3(2*DIMN/BN, Mm/BM), 256>>>(xn, wkv, nullptr, kv, 2*DIMN);
    pos_kernel<<<dim3(NJ/64, Cc), 256, 68864>>>();
    attn_kernel<<<NJ, 256, 136448>>>();
    gemm_tf32<<<dim3(DIMN/BN, Mm/BM), 256>>>(att, wo, bo, out, DIMN);
}